// round 14
// baseline (speedup 1.0000x reference)
#include <cuda_runtime.h>
#include <cuda_bf16.h>
#include <math.h>
#include <stdint.h>

#define NQ 6
#define NL 3

typedef uint32_t u32;

// ==================== device globals ====================
__device__ __align__(16) float g_Gr[64][64];
__device__ __align__(16) float g_Gi[64][64];
__device__ float g_G[3][64];
__device__ float g_d[3];
// split-K partial C scratch: [khalf][row][col], 8 MB
__device__ __align__(16) float g_C[2][16384][64];

// ---- kernel 0: build 64x64 evolution matrix (4 blocks x 16 columns) ----
__global__ __launch_bounds__(256) void precompute_kernel(const float* __restrict__ qw,
                                                         const float* __restrict__ Wq,
                                                         const float* __restrict__ bq,
                                                         const float* __restrict__ Wf,
                                                         const float* __restrict__ bf) {
    __shared__ float Mr[64][17];
    __shared__ float Mi[64][17];
    __shared__ float2 sU[NL * NQ][4];
    __shared__ float sA[3][NQ];
    const int t = threadIdx.x;
    const int col0 = blockIdx.x * 16;

    if (t < NL * NQ) {
        float phi = qw[t * 3 + 0], th = qw[t * 3 + 1], om = qw[t * 3 + 2];
        float s2, c2;  sincosf(0.5f * th, &s2, &c2);
        float spo, cpo; sincosf(0.5f * (phi + om), &spo, &cpo);
        float smo, cmo; sincosf(0.5f * (phi - om), &smo, &cmo);
        sU[t][0] = make_float2( cpo * c2, -spo * c2);
        sU[t][1] = make_float2(-cmo * s2, -smo * s2);
        sU[t][2] = make_float2( cmo * s2, -smo * s2);
        sU[t][3] = make_float2( cpo * c2,  spo * c2);
    }
    if (blockIdx.x == 0 && t >= 32 && t < 50) {
        int u = t - 32, j = u / 6, w = u % 6;
        float a = 0.f;
        for (int k = 0; k < 16; k++) a += Wf[j * 80 + 64 + k] * Wq[k * 6 + w];
        sA[j][w] = a;
    }
    for (int idx = t; idx < 1024; idx += 256) {
        int r = idx >> 4, c = idx & 15;
        Mr[r][c] = (r == col0 + c) ? 1.f : 0.f;
        Mi[r][c] = 0.f;
    }
    __syncthreads();

    for (int l = 0; l < NL; l++) {
        for (int w = 0; w < NQ; w++) {
            float2 u00 = sU[l * NQ + w][0], u01 = sU[l * NQ + w][1];
            float2 u10 = sU[l * NQ + w][2], u11 = sU[l * NQ + w][3];
            const int bit = 1 << (5 - w);
            for (int v = t; v < 512; v += 256) {
                int p = v >> 4, c = v & 15;
                int i = ((p & ~(bit - 1)) << 1) | (p & (bit - 1));
                int j = i | bit;
                float ar = Mr[i][c], ai = Mi[i][c], br = Mr[j][c], bi = Mi[j][c];
                Mr[i][c] = u00.x * ar - u00.y * ai + u01.x * br - u01.y * bi;
                Mi[i][c] = u00.x * ai + u00.y * ar + u01.x * bi + u01.y * br;
                Mr[j][c] = u10.x * ar - u10.y * ai + u11.x * br - u11.y * bi;
                Mi[j][c] = u10.x * ai + u10.y * ar + u11.x * bi + u11.y * br;
            }
            __syncthreads();
        }
        const int r = (l % (NQ - 1)) + 1;
        for (int w = 0; w < NQ; w++) {
            const int tq = (w + r) % NQ;
            const int cbit = 1 << (5 - w);
            const int tbit = 1 << (5 - tq);
            const int lo_b = cbit < tbit ? cbit : tbit;
            const int hi_b = cbit < tbit ? tbit : cbit;
            for (int v = t; v < 256; v += 256) {
                int x = v >> 4, c = v & 15;
                int t1 = ((x & ~(lo_b - 1)) << 1) | (x & (lo_b - 1));
                int i0 = ((t1 & ~(hi_b - 1)) << 1) | (t1 & (hi_b - 1));
                int i = i0 | cbit;
                int j = i | tbit;
                float tr = Mr[i][c]; Mr[i][c] = Mr[j][c]; Mr[j][c] = tr;
                float ti = Mi[i][c]; Mi[i][c] = Mi[j][c]; Mi[j][c] = ti;
            }
            __syncthreads();
        }
    }

    for (int idx = t; idx < 1024; idx += 256) {
        int r = idx >> 4, c = idx & 15;
        g_Gr[r][col0 + c] = Mr[r][c];
        g_Gi[r][col0 + c] = Mi[r][c];
    }
    if (blockIdx.x == 0) {
        for (int i = t; i < 192; i += 256) {
            int j = i >> 6, s = i & 63;
            float g = 0.f;
            #pragma unroll
            for (int w = 0; w < 6; w++)
                g += sA[j][w] * (((s >> (5 - w)) & 1) ? -1.f : 1.f);
            g_G[j][s] = g;
        }
        if (t < 3) {
            float v = bf[t];
            for (int k = 0; k < 16; k++) v += Wf[t * 80 + 64 + k] * bq[k];
            g_d[t] = v;
        }
    }
}

// ==================== split-K GEMM (mma.sync bf16-split) ====================
// Tile M64 x N64, KC 32, K split in 2 halves of 1024; grid = 512 (256 m-tiles x 2 k-halves).
#define KC 32
#define NCHUNK_H 32
#define BUF_A_HI 0
#define BUF_A_LO 4096
#define BUF_B_HI 8192
#define BUF_B_LO 12288
#define BUFSZ 16384
#define RING (3 * BUFSZ)
#define GEMM_DSMEM (1024 + RING)

__device__ __forceinline__ u32 smem_u32(const void* p) {
    u32 a;
    asm("{ .reg .u64 t; cvta.to.shared.u64 t, %1; cvt.u32.u64 %0, t; }" : "=r"(a) : "l"(p));
    return a;
}

// XOR-swizzled offset for a [rows][KC] bf16 tile packed 2 rows per 128B line.
__device__ __forceinline__ u32 aoff(u32 row, u32 k) {
    u32 o = ((row >> 1) << 7) | ((row & 1) << 6) | (k << 1);
    return o ^ (((row >> 1) & 7) << 4);
}

#define LDMX4(r0, r1, r2, r3, addr) \
    asm volatile("ldmatrix.sync.aligned.m8n8.x4.shared.b16 {%0,%1,%2,%3}, [%4];" \
        : "=r"(r0), "=r"(r1), "=r"(r2), "=r"(r3) : "r"(addr))

#define MMA16816(d, a, b0, b1) \
    asm volatile("mma.sync.aligned.m16n8k16.row.col.f32.bf16.bf16.f32 " \
        "{%0,%1,%2,%3}, {%4,%5,%6,%7}, {%8,%9}, {%0,%1,%2,%3};" \
        : "+f"((d)[0]), "+f"((d)[1]), "+f"((d)[2]), "+f"((d)[3]) \
        : "r"((a)[0]), "r"((a)[1]), "r"((a)[2]), "r"((a)[3]), "r"(b0), "r"(b1))

__device__ __forceinline__ void split4(u32 hi_addr, u32 lo_addr, float4 v) {
    u32 b0 = __float_as_uint(v.x), b1 = __float_as_uint(v.y);
    u32 b2 = __float_as_uint(v.z), b3 = __float_as_uint(v.w);
    u32 h01 = __byte_perm(b0, b1, 0x7632);
    u32 h23 = __byte_perm(b2, b3, 0x7632);
    float l0 = v.x - __uint_as_float(b0 & 0xFFFF0000u);
    float l1 = v.y - __uint_as_float(b1 & 0xFFFF0000u);
    float l2 = v.z - __uint_as_float(b2 & 0xFFFF0000u);
    float l3 = v.w - __uint_as_float(b3 & 0xFFFF0000u);
    u32 L01, L23;
    asm("cvt.rn.bf16x2.f32 %0, %1, %2;" : "=r"(L01) : "f"(l1), "f"(l0));
    asm("cvt.rn.bf16x2.f32 %0, %1, %2;" : "=r"(L23) : "f"(l3), "f"(l2));
    asm volatile("st.shared.v2.b32 [%0], {%1,%2};" :: "r"(hi_addr), "r"(h01), "r"(h23) : "memory");
    asm volatile("st.shared.v2.b32 [%0], {%1,%2};" :: "r"(lo_addr), "r"(L01), "r"(L23) : "memory");
}

__global__ __launch_bounds__(128, 4) void gemm_kernel(const float* __restrict__ xc,
                                                      const float* __restrict__ W1) {
    extern __shared__ char dyn_smem[];
    const u32 sb = smem_u32(dyn_smem);
    const u32 ring = (sb + 1023u) & ~1023u;

    const int tid = threadIdx.x;
    const int lane = tid & 31;
    const int warp = tid >> 5;
    const int mtile = blockIdx.x & 255;
    const int khalf = blockIdx.x >> 8;
    const int row0 = mtile * 64;
    const int kbase = khalf * 1024;
    const int mh = (warp & 1) * 32;   // m-half base
    const int n0 = (warp >> 1) * 32;  // n-half base

    // loader coords: 512 float4 per matrix per chunk, 4 per thread
    int lrow[4], lk[4];
    #pragma unroll
    for (int g = 0; g < 4; g++) {
        int f = g * 128 + tid;
        lrow[g] = f >> 3;
        lk[g] = (f & 7) * 4;
    }

    float4 pa[4], pb[4];
    float acc[2][4][4];
    #pragma unroll
    for (int mt = 0; mt < 2; mt++)
        #pragma unroll
        for (int nt = 0; nt < 4; nt++)
            #pragma unroll
            for (int e = 0; e < 4; e++) acc[mt][nt][e] = 0.f;

    const u32 arow = (u32)(mh + (lane & 7) + ((lane >> 3) & 1) * 8);
    const u32 akof = (u32)((lane >> 4) * 8);
    const u32 brow_base = (u32)((lane & 7) + (lane >> 4) * 8);
    const u32 bkof = (u32)(((lane >> 3) & 1) * 8);

#define LOAD_CHUNK(kc) do { \
    _Pragma("unroll") \
    for (int g = 0; g < 4; g++) { \
        pa[g] = *(const float4*)(xc + (size_t)(row0 + lrow[g]) * 2048 + (kc) + lk[g]); \
        pb[g] = *(const float4*)(W1 + (size_t)lrow[g] * 2048 + (kc) + lk[g]); \
    } } while (0)

#define STORE_CHUNK(bufb) do { \
    _Pragma("unroll") \
    for (int g = 0; g < 4; g++) { \
        u32 o = aoff((u32)lrow[g], (u32)lk[g]); \
        split4((bufb) + BUF_A_HI + o, (bufb) + BUF_A_LO + o, pa[g]); \
        split4((bufb) + BUF_B_HI + o, (bufb) + BUF_B_LO + o, pb[g]); \
    } } while (0)

    LOAD_CHUNK(kbase);
    STORE_CHUNK(ring);
    LOAD_CHUNK(kbase + KC);
    STORE_CHUNK(ring + BUFSZ);
    LOAD_CHUNK(kbase + 2 * KC);
    __syncthreads();

    #pragma unroll 1
    for (int i = 0; i < NCHUNK_H; i++) {
        if (i + 2 < NCHUNK_H) {
            STORE_CHUNK(ring + ((i + 2) % 3) * BUFSZ);
        }
        if (i + 3 < NCHUNK_H) {
            LOAD_CHUNK(kbase + (i + 3) * KC);
        }
        const u32 bb = ring + (i % 3) * BUFSZ;
        #pragma unroll
        for (int ks = 0; ks < 2; ks++) {
            u32 ah[2][4], al[2][4], bh[2][4], bl[2][4];
            #pragma unroll
            for (int mt = 0; mt < 2; mt++) {
                u32 a_ = bb + aoff(arow + (u32)(mt * 16), (u32)(ks * 16) + akof);
                LDMX4(ah[mt][0], ah[mt][1], ah[mt][2], ah[mt][3], a_ + BUF_A_HI);
                LDMX4(al[mt][0], al[mt][1], al[mt][2], al[mt][3], a_ + BUF_A_LO);
            }
            #pragma unroll
            for (int g = 0; g < 2; g++) {
                u32 b_ = bb + aoff((u32)(n0 + g * 16) + brow_base, (u32)(ks * 16) + bkof);
                LDMX4(bh[g][0], bh[g][1], bh[g][2], bh[g][3], b_ + BUF_B_HI);
                LDMX4(bl[g][0], bl[g][1], bl[g][2], bl[g][3], b_ + BUF_B_LO);
            }
            // B-style lane mapping (brow_base/bkof) fragment ordering:
            //   frag0=(n-lo,k-lo) frag1=(n-lo,k-hi) frag2=(n-hi,k-lo) frag3=(n-hi,k-hi)
            // -> MMA b-operand pair for n-subtile (nt&1) is CONSECUTIVE:
            //    {frag[2*(nt&1)], frag[2*(nt&1)+1]}   (R9/R12-verified)
            #pragma unroll
            for (int mt = 0; mt < 2; mt++)
                #pragma unroll
                for (int nt = 0; nt < 4; nt++) {
                    const int g = nt >> 1, p = (nt & 1) * 2;
                    MMA16816(acc[mt][nt], ah[mt], bh[g][p], bh[g][p + 1]);
                    MMA16816(acc[mt][nt], ah[mt], bl[g][p], bl[g][p + 1]);
                    MMA16816(acc[mt][nt], al[mt], bh[g][p], bh[g][p + 1]);
                }
        }
        __syncthreads();
    }

    // ---- store partial C (pre-bias) to scratch; warps own disjoint 32x32 quadrants ----
    // acc[mt][nt] covers rows (mh + mt*16 + lane>>2, +8), cols n0 + nt*8 + 2*(lane&3) {+1}
    #pragma unroll
    for (int mt = 0; mt < 2; mt++) {
        const int r0 = row0 + mh + mt * 16 + (lane >> 2);
        #pragma unroll
        for (int nt = 0; nt < 4; nt++) {
            const int c0 = n0 + nt * 8 + 2 * (lane & 3);
            *(float2*)&g_C[khalf][r0][c0]     = make_float2(acc[mt][nt][0], acc[mt][nt][1]);
            *(float2*)&g_C[khalf][r0 + 8][c0] = make_float2(acc[mt][nt][2], acc[mt][nt][3]);
        }
    }
}

// ==================== epilogue: combine halves + bias + relu + Wf fold + quantum ====================
__global__ __launch_bounds__(128) void epi_kernel(const float* __restrict__ b1,
                                                  const float* __restrict__ Wf,
                                                  const float* __restrict__ xq,
                                                  float* __restrict__ out) {
    __shared__ float sGr[64][64];
    __shared__ float sGi[64][64];
    __shared__ float sG[192];
    __shared__ float sWf[192];
    __shared__ float sB1[64];
    __shared__ float sd[4];

    const int tid = threadIdx.x;
    const int row0 = blockIdx.x * 64;

    for (int i = tid; i < 4096; i += 128) {
        ((float*)sGr)[i] = ((const float*)g_Gr)[i];
        ((float*)sGi)[i] = ((const float*)g_Gi)[i];
    }
    for (int i = tid; i < 192; i += 128) {
        sG[i]  = ((const float*)g_G)[i];
        sWf[i] = Wf[(i >> 6) * 80 + (i & 63)];
    }
    if (tid < 64) sB1[tid] = b1[tid];
    if (tid >= 64 && tid < 68) sd[tid - 64] = g_d[tid - 64];
    __syncthreads();

    const int sl = tid >> 1;
    const int half = tid & 1;
    const int row = row0 + sl;

    // ---- gemm fold over this thread's 32 columns ----
    float o0 = 0.f, o1 = 0.f, o2 = 0.f;
    {
        const int cbase = half * 32;
        const float4* p0 = (const float4*)&g_C[0][row][cbase];
        const float4* p1 = (const float4*)&g_C[1][row][cbase];
        #pragma unroll
        for (int q = 0; q < 8; q++) {
            float4 v0 = p0[q], v1 = p1[q];
            #pragma unroll
            for (int e = 0; e < 4; e++) {
                const int c = cbase + q * 4 + e;
                float v = (e == 0 ? v0.x + v1.x : e == 1 ? v0.y + v1.y :
                           e == 2 ? v0.z + v1.z : v0.w + v1.w) + sB1[c];
                v = v > 0.f ? v : 0.f;
                o0 += v * sWf[c];
                o1 += v * sWf[64 + c];
                o2 += v * sWf[128 + c];
            }
        }
    }

    // ---- quantum part for this thread's 32 states ----
    {
        float csq[NQ], snq[NQ];
        #pragma unroll
        for (int q = 0; q < NQ; q++) sincosf(0.5f * xq[row * NQ + q], &snq[q], &csq[q]);

        float a[64];
        a[0] = csq[0]; a[1] = snq[0];
        #pragma unroll
        for (int q = 1; q < NQ; q++) {
            const int n = 1 << q;
            #pragma unroll 32
            for (int j = n - 1; j >= 0; j--) {
                float v = a[j];
                a[2 * j]     = v * csq[q];
                a[2 * j + 1] = v * snq[q];
            }
        }

        const int s0 = half * 32;
        #pragma unroll 2
        for (int ss = 0; ss < 32; ss++) {
            const int s = s0 + ss;
            const float4* gr = (const float4*)sGr[s];
            const float4* gi = (const float4*)sGi[s];
            float yr0 = 0.f, yr1 = 0.f, yi0 = 0.f, yi1 = 0.f;
            #pragma unroll
            for (int t4 = 0; t4 < 16; t4++) {
                float4 g1 = gr[t4], g2 = gi[t4];
                const float* av = &a[t4 * 4];
                yr0 += g1.x * av[0]; yr1 += g1.y * av[1];
                yr0 += g1.z * av[2]; yr1 += g1.w * av[3];
                yi0 += g2.x * av[0]; yi1 += g2.y * av[1];
                yi0 += g2.z * av[2]; yi1 += g2.w * av[3];
            }
            float yr = yr0 + yr1, yi = yi0 + yi1;
            float p = yr * yr + yi * yi;
            o0 += p * sG[s];
            o1 += p * sG[64 + s];
            o2 += p * sG[128 + s];
        }
    }

    o0 += __shfl_xor_sync(0xFFFFFFFFu, o0, 1);
    o1 += __shfl_xor_sync(0xFFFFFFFFu, o1, 1);
    o2 += __shfl_xor_sync(0xFFFFFFFFu, o2, 1);

    if (half == 0) {
        const size_t o = (size_t)row * 3;
        out[o + 0] = o0 + sd[0];
        out[o + 1] = o1 + sd[1];
        out[o + 2] = o2 + sd[2];
    }
}

// ==================== launch ====================
extern "C" void kernel_launch(void* const* d_in, const int* in_sizes, int n_in,
                              void* d_out, int out_size) {
    const float* xc = (const float*)d_in[0];
    const float* xq = (const float*)d_in[1];
    const float* W1 = (const float*)d_in[2];
    const float* b1 = (const float*)d_in[3];
    const float* qw = (const float*)d_in[4];
    const float* Wq = (const float*)d_in[5];
    const float* bq = (const float*)d_in[6];
    const float* Wf = (const float*)d_in[7];
    const float* bf = (const float*)d_in[8];
    float* out = (float*)d_out;

    const int B = in_sizes[0] / 2048;  // 16384

    static int configured = 0;
    if (!configured) {
        cudaFuncSetAttribute(gemm_kernel, cudaFuncAttributeMaxDynamicSharedMemorySize, GEMM_DSMEM);
        configured = 1;
    }

    precompute_kernel<<<4, 256>>>(qw, Wq, bq, Wf, bf);
    gemm_kernel<<<(B / 64) * 2, 128, GEMM_DSMEM>>>(xc, W1);
    epi_kernel<<<B / 64, 128>>>(b1, Wf, xq, out);
}

// round 15
// speedup vs baseline: 1.1903x; 1.1903x over previous
#include <cuda_runtime.h>
#include <cuda_bf16.h>
#include <math.h>
#include <stdint.h>

#define NQ 6
#define NL 3

typedef uint32_t u32;

// ==================== quantum tables ====================
__device__ __align__(16) float g_Gr[64][64];
__device__ __align__(16) float g_Gi[64][64];
__device__ float g_G[3][64];
__device__ float g_d[3];

// ---- kernel 0: build 64x64 evolution matrix (32 blocks x 2 columns, 64 threads) ----
__global__ __launch_bounds__(64) void precompute_kernel(const float* __restrict__ qw,
                                                        const float* __restrict__ Wq,
                                                        const float* __restrict__ bq,
                                                        const float* __restrict__ Wf,
                                                        const float* __restrict__ bf) {
    __shared__ float Mr[64][2];
    __shared__ float Mi[64][2];
    __shared__ float2 sU[NL * NQ][4];
    __shared__ float sA[3][NQ];
    const int t = threadIdx.x;
    const int col0 = blockIdx.x * 2;

    if (t < NL * NQ) {
        float phi = qw[t * 3 + 0], th = qw[t * 3 + 1], om = qw[t * 3 + 2];
        float s2, c2;  sincosf(0.5f * th, &s2, &c2);
        float spo, cpo; sincosf(0.5f * (phi + om), &spo, &cpo);
        float smo, cmo; sincosf(0.5f * (phi - om), &smo, &cmo);
        sU[t][0] = make_float2( cpo * c2, -spo * c2);
        sU[t][1] = make_float2(-cmo * s2, -smo * s2);
        sU[t][2] = make_float2( cmo * s2, -smo * s2);
        sU[t][3] = make_float2( cpo * c2,  spo * c2);
    }
    if (blockIdx.x == 0 && t >= 32 && t < 50) {
        int u = t - 32, j = u / 6, w = u % 6;
        float a = 0.f;
        for (int k = 0; k < 16; k++) a += Wf[j * 80 + 64 + k] * Wq[k * 6 + w];
        sA[j][w] = a;
    }
    for (int idx = t; idx < 128; idx += 64) {
        int r = idx >> 1, c = idx & 1;
        Mr[r][c] = (r == col0 + c) ? 1.f : 0.f;
        Mi[r][c] = 0.f;
    }
    __syncthreads();

    for (int l = 0; l < NL; l++) {
        for (int w = 0; w < NQ; w++) {
            float2 u00 = sU[l * NQ + w][0], u01 = sU[l * NQ + w][1];
            float2 u10 = sU[l * NQ + w][2], u11 = sU[l * NQ + w][3];
            const int bit = 1 << (5 - w);
            {
                int v = t;  // 64 updates, 1 per thread
                int p = v >> 1, c = v & 1;
                int i = ((p & ~(bit - 1)) << 1) | (p & (bit - 1));
                int j = i | bit;
                float ar = Mr[i][c], ai = Mi[i][c], br = Mr[j][c], bi = Mi[j][c];
                Mr[i][c] = u00.x * ar - u00.y * ai + u01.x * br - u01.y * bi;
                Mi[i][c] = u00.x * ai + u00.y * ar + u01.x * bi + u01.y * br;
                Mr[j][c] = u10.x * ar - u10.y * ai + u11.x * br - u11.y * bi;
                Mi[j][c] = u10.x * ai + u10.y * ar + u11.x * bi + u11.y * br;
            }
            __syncthreads();
        }
        const int r = (l % (NQ - 1)) + 1;
        for (int w = 0; w < NQ; w++) {
            const int tq = (w + r) % NQ;
            const int cbit = 1 << (5 - w);
            const int tbit = 1 << (5 - tq);
            const int lo_b = cbit < tbit ? cbit : tbit;
            const int hi_b = cbit < tbit ? tbit : cbit;
            if (t < 32) {
                int x = t >> 1, c = t & 1;
                int t1 = ((x & ~(lo_b - 1)) << 1) | (x & (lo_b - 1));
                int i0 = ((t1 & ~(hi_b - 1)) << 1) | (t1 & (hi_b - 1));
                int i = i0 | cbit;
                int j = i | tbit;
                float tr = Mr[i][c]; Mr[i][c] = Mr[j][c]; Mr[j][c] = tr;
                float ti = Mi[i][c]; Mi[i][c] = Mi[j][c]; Mi[j][c] = ti;
            }
            __syncthreads();
        }
    }

    for (int idx = t; idx < 128; idx += 64) {
        int r = idx >> 1, c = idx & 1;
        g_Gr[r][col0 + c] = Mr[r][c];
        g_Gi[r][col0 + c] = Mi[r][c];
    }
    if (blockIdx.x == 0) {
        for (int i = t; i < 192; i += 64) {
            int j = i >> 6, s = i & 63;
            float g = 0.f;
            #pragma unroll
            for (int w = 0; w < 6; w++)
                g += sA[j][w] * (((s >> (5 - w)) & 1) ? -1.f : 1.f);
            g_G[j][s] = g;
        }
        if (t < 3) {
            float v = bf[t];
            for (int k = 0; k < 16; k++) v += Wf[t * 80 + 64 + k] * bq[k];
            g_d[t] = v;
        }
    }
}

// ==================== fused GEMM (mma.sync bf16-split) + quantum epilogue ====================
// Tile M64 x N64, KC 32, 128 threads = 4 warps (M16xN64 per warp), depth-4 ring,
// __syncthreads only after odd iters (proven-safe: in-flight stores and reads
// touch disjoint ring slots within any [2k, 2k+1] iteration window).
#define KC 32
#define NCHUNK 64
#define BUF_A_HI 0
#define BUF_A_LO 4096
#define BUF_B_HI 8192
#define BUF_B_LO 12288
#define BUFSZ 16384
#define RING (4 * BUFSZ)
#define GEMM_DSMEM (1024 + RING)

__device__ __forceinline__ u32 smem_u32(const void* p) {
    u32 a;
    asm("{ .reg .u64 t; cvta.to.shared.u64 t, %1; cvt.u32.u64 %0, t; }" : "=r"(a) : "l"(p));
    return a;
}

// XOR-swizzled offset for a [rows][KC] bf16 tile packed 2 rows per 128B line.
__device__ __forceinline__ u32 aoff(u32 row, u32 k) {
    u32 o = ((row >> 1) << 7) | ((row & 1) << 6) | (k << 1);
    return o ^ (((row >> 1) & 7) << 4);
}

#define LDMX4(r0, r1, r2, r3, addr) \
    asm volatile("ldmatrix.sync.aligned.m8n8.x4.shared.b16 {%0,%1,%2,%3}, [%4];" \
        : "=r"(r0), "=r"(r1), "=r"(r2), "=r"(r3) : "r"(addr))

#define MMA16816(d, a, b0, b1) \
    asm volatile("mma.sync.aligned.m16n8k16.row.col.f32.bf16.bf16.f32 " \
        "{%0,%1,%2,%3}, {%4,%5,%6,%7}, {%8,%9}, {%0,%1,%2,%3};" \
        : "+f"((d)[0]), "+f"((d)[1]), "+f"((d)[2]), "+f"((d)[3]) \
        : "r"((a)[0]), "r"((a)[1]), "r"((a)[2]), "r"((a)[3]), "r"(b0), "r"(b1))

__device__ __forceinline__ void split4(u32 hi_addr, u32 lo_addr, float4 v) {
    u32 b0 = __float_as_uint(v.x), b1 = __float_as_uint(v.y);
    u32 b2 = __float_as_uint(v.z), b3 = __float_as_uint(v.w);
    u32 h01 = __byte_perm(b0, b1, 0x7632);
    u32 h23 = __byte_perm(b2, b3, 0x7632);
    float l0 = v.x - __uint_as_float(b0 & 0xFFFF0000u);
    float l1 = v.y - __uint_as_float(b1 & 0xFFFF0000u);
    float l2 = v.z - __uint_as_float(b2 & 0xFFFF0000u);
    float l3 = v.w - __uint_as_float(b3 & 0xFFFF0000u);
    u32 L01, L23;
    asm("cvt.rn.bf16x2.f32 %0, %1, %2;" : "=r"(L01) : "f"(l1), "f"(l0));
    asm("cvt.rn.bf16x2.f32 %0, %1, %2;" : "=r"(L23) : "f"(l3), "f"(l2));
    asm volatile("st.shared.v2.b32 [%0], {%1,%2};" :: "r"(hi_addr), "r"(h01), "r"(h23) : "memory");
    asm volatile("st.shared.v2.b32 [%0], {%1,%2};" :: "r"(lo_addr), "r"(L01), "r"(L23) : "memory");
}

__global__ __launch_bounds__(128, 3) void fused_kernel(const float* __restrict__ xc,
                                                       const float* __restrict__ W1,
                                                       const float* __restrict__ b1,
                                                       const float* __restrict__ Wf,
                                                       const float* __restrict__ xq,
                                                       float* __restrict__ out) {
    extern __shared__ char dyn_smem[];
    __shared__ float sG[192];
    __shared__ float sWf[192];
    __shared__ float sB1[64];
    __shared__ float sd[4];
    __shared__ float sQ[192];

    const u32 sb = smem_u32(dyn_smem);
    const u32 ring = (sb + 1023u) & ~1023u;
    char* rbase = dyn_smem + (ring - sb);

    const int tid = threadIdx.x;
    const int lane = tid & 31;
    const int warp = tid >> 5;
    const int row0 = blockIdx.x * 64;
    const int m0 = warp * 16;

    // small tables (static smem)
    for (int i = tid; i < 192; i += 128) {
        sG[i]  = ((const float*)g_G)[i];
        sWf[i] = Wf[(i >> 6) * 80 + (i & 63)];
    }
    if (tid < 64) sB1[tid] = b1[tid];
    if (tid >= 64 && tid < 68) sd[tid - 64] = g_d[tid - 64];

    // loader coords: 512 float4 per matrix per chunk, 4 per thread
    int lrow[4], lk[4];
    #pragma unroll
    for (int g = 0; g < 4; g++) {
        int f = g * 128 + tid;
        lrow[g] = f >> 3;
        lk[g] = (f & 7) * 4;
    }

    float4 pa[4], pb[4];
    float acc[8][4];
    #pragma unroll
    for (int nt = 0; nt < 8; nt++)
        #pragma unroll
        for (int e = 0; e < 4; e++) acc[nt][e] = 0.f;

    const u32 arow = (u32)(m0 + (lane & 7) + ((lane >> 3) & 1) * 8);
    const u32 akof = (u32)((lane >> 4) * 8);
    const u32 brow_base = (u32)((lane & 7) + (lane >> 4) * 8);
    const u32 bkof = (u32)(((lane >> 3) & 1) * 8);

#define LOAD_CHUNK(kc) do { \
    _Pragma("unroll") \
    for (int g = 0; g < 4; g++) { \
        pa[g] = *(const float4*)(xc + (size_t)(row0 + lrow[g]) * 2048 + (kc) + lk[g]); \
        pb[g] = *(const float4*)(W1 + (size_t)lrow[g] * 2048 + (kc) + lk[g]); \
    } } while (0)

#define STORE_CHUNK(bufb) do { \
    _Pragma("unroll") \
    for (int g = 0; g < 4; g++) { \
        u32 o = aoff((u32)lrow[g], (u32)lk[g]); \
        split4((bufb) + BUF_A_HI + o, (bufb) + BUF_A_LO + o, pa[g]); \
        split4((bufb) + BUF_B_HI + o, (bufb) + BUF_B_LO + o, pb[g]); \
    } } while (0)

    LOAD_CHUNK(0);
    STORE_CHUNK(ring);
    LOAD_CHUNK(KC);
    STORE_CHUNK(ring + BUFSZ);
    LOAD_CHUNK(2 * KC);
    __syncthreads();

    #pragma unroll 1
    for (int i = 0; i < NCHUNK; i++) {
        if (i + 2 < NCHUNK) {
            STORE_CHUNK(ring + ((i + 2) & 3) * BUFSZ);
        }
        if (i + 3 < NCHUNK) {
            LOAD_CHUNK((i + 3) * KC);
        }
        const u32 bb = ring + (i & 3) * BUFSZ;
        #pragma unroll
        for (int ks = 0; ks < 2; ks++) {
            u32 ah[4], al[4];
            u32 aaddr = aoff(arow, (u32)(ks * 16) + akof);
            LDMX4(ah[0], ah[1], ah[2], ah[3], bb + BUF_A_HI + aaddr);
            LDMX4(al[0], al[1], al[2], al[3], bb + BUF_A_LO + aaddr);
            u32 bh[16], bl[16];
            #pragma unroll
            for (int g = 0; g < 4; g++) {
                u32 baddr = aoff((u32)(g * 16) + brow_base, (u32)(ks * 16) + bkof);
                LDMX4(bh[4 * g], bh[4 * g + 1], bh[4 * g + 2], bh[4 * g + 3], bb + BUF_B_HI + baddr);
                LDMX4(bl[4 * g], bl[4 * g + 1], bl[4 * g + 2], bl[4 * g + 3], bb + BUF_B_LO + baddr);
            }
            // B-style mapping: frag order (n-lo,k-lo)(n-lo,k-hi)(n-hi,k-lo)(n-hi,k-hi)
            // -> consecutive pairs {2nt, 2nt+1} (R9-verified)
            #pragma unroll
            for (int nt = 0; nt < 8; nt++) {
                MMA16816(acc[nt], ah, bh[2 * nt], bh[2 * nt + 1]);
                MMA16816(acc[nt], ah, bl[2 * nt], bl[2 * nt + 1]);
                MMA16816(acc[nt], al, bh[2 * nt], bh[2 * nt + 1]);
            }
        }
        if (i & 1) __syncthreads();   // depth-4 ring: sync every 2 chunks suffices
    }

    // ---- gemm partial: relu(acc + b1) . Wf, reduce over 4-lane column group ----
    float o[2][3] = {{0.f, 0.f, 0.f}, {0.f, 0.f, 0.f}};
    #pragma unroll
    for (int nt = 0; nt < 8; nt++) {
        const int n0 = nt * 8 + 2 * (lane & 3);
        const int n1 = n0 + 1;
        const float bb0 = sB1[n0], bb1 = sB1[n1];
        float c00 = acc[nt][0] + bb0; c00 = c00 > 0.f ? c00 : 0.f;
        float c01 = acc[nt][1] + bb1; c01 = c01 > 0.f ? c01 : 0.f;
        float c10 = acc[nt][2] + bb0; c10 = c10 > 0.f ? c10 : 0.f;
        float c11 = acc[nt][3] + bb1; c11 = c11 > 0.f ? c11 : 0.f;
        #pragma unroll
        for (int j = 0; j < 3; j++) {
            o[0][j] += c00 * sWf[j * 64 + n0] + c01 * sWf[j * 64 + n1];
            o[1][j] += c10 * sWf[j * 64 + n0] + c11 * sWf[j * 64 + n1];
        }
    }
    #pragma unroll
    for (int r = 0; r < 2; r++)
        #pragma unroll
        for (int j = 0; j < 3; j++) {
            o[r][j] += __shfl_xor_sync(0xFFFFFFFFu, o[r][j], 1);
            o[r][j] += __shfl_xor_sync(0xFFFFFFFFu, o[r][j], 2);
        }

    // ---- copy G tables into the dead ring (64KB >= 32KB) ----
    float* sGr = (float*)rbase;            // 16KB
    float* sGi = sGr + 4096;               // 16KB
    {
        const float4* gr4 = (const float4*)g_Gr;
        const float4* gi4 = (const float4*)g_Gi;
        float4* dr = (float4*)sGr;
        float4* di = (float4*)sGi;
        for (int i = tid; i < 1024; i += 128) { dr[i] = gr4[i]; di[i] = gi4[i]; }
    }
    __syncthreads();

    // ---- quantum part: 2 threads per sample, s-range split ----
    {
        const int sl = tid >> 1;
        const int half = tid & 1;
        const int sample = row0 + sl;
        float csq[NQ], snq[NQ];
        #pragma unroll
        for (int q = 0; q < NQ; q++) sincosf(0.5f * xq[sample * NQ + q], &snq[q], &csq[q]);

        float a[64];
        a[0] = csq[0]; a[1] = snq[0];
        #pragma unroll
        for (int q = 1; q < NQ; q++) {
            const int n = 1 << q;
            #pragma unroll 32
            for (int j = n - 1; j >= 0; j--) {
                float v = a[j];
                a[2 * j]     = v * csq[q];
                a[2 * j + 1] = v * snq[q];
            }
        }

        float q0 = 0.f, q1 = 0.f, q2 = 0.f;
        const int s0 = half * 32;
        #pragma unroll 2
        for (int ss = 0; ss < 32; ss++) {
            const int s = s0 + ss;
            const float4* gr = (const float4*)(sGr + s * 64);
            const float4* gi = (const float4*)(sGi + s * 64);
            float yr0 = 0.f, yr1 = 0.f, yi0 = 0.f, yi1 = 0.f;
            #pragma unroll
            for (int t4 = 0; t4 < 16; t4++) {
                float4 g1 = gr[t4], g2 = gi[t4];
                const float* av = &a[t4 * 4];
                yr0 += g1.x * av[0]; yr1 += g1.y * av[1];
                yr0 += g1.z * av[2]; yr1 += g1.w * av[3];
                yi0 += g2.x * av[0]; yi1 += g2.y * av[1];
                yi0 += g2.z * av[2]; yi1 += g2.w * av[3];
            }
            float yr = yr0 + yr1, yi = yi0 + yi1;
            float p = yr * yr + yi * yi;
            q0 += p * sG[s];
            q1 += p * sG[64 + s];
            q2 += p * sG[128 + s];
        }
        q0 += __shfl_xor_sync(0xFFFFFFFFu, q0, 1);
        q1 += __shfl_xor_sync(0xFFFFFFFFu, q1, 1);
        q2 += __shfl_xor_sync(0xFFFFFFFFu, q2, 1);
        if (half == 0) {
            sQ[sl * 3 + 0] = q0 + sd[0];
            sQ[sl * 3 + 1] = q1 + sd[1];
            sQ[sl * 3 + 2] = q2 + sd[2];
        }
    }
    __syncthreads();

    if ((lane & 3) == 0) {
        const int lr0 = m0 + (lane >> 2);
        const int gr0 = row0 + lr0;
        #pragma unroll
        for (int j = 0; j < 3; j++) {
            out[(size_t)gr0 * 3 + j]       = o[0][j] + sQ[lr0 * 3 + j];
            out[(size_t)(gr0 + 8) * 3 + j] = o[1][j] + sQ[(lr0 + 8) * 3 + j];
        }
    }
}

// ==================== launch ====================
extern "C" void kernel_launch(void* const* d_in, const int* in_sizes, int n_in,
                              void* d_out, int out_size) {
    const float* xc = (const float*)d_in[0];
    const float* xq = (const float*)d_in[1];
    const float* W1 = (const float*)d_in[2];
    const float* b1 = (const float*)d_in[3];
    const float* qw = (const float*)d_in[4];
    const float* Wq = (const float*)d_in[5];
    const float* bq = (const float*)d_in[6];
    const float* Wf = (const float*)d_in[7];
    const float* bf = (const float*)d_in[8];
    float* out = (float*)d_out;

    const int B = in_sizes[0] / 2048;  // 16384

    static int configured = 0;
    if (!configured) {
        cudaFuncSetAttribute(fused_kernel, cudaFuncAttributeMaxDynamicSharedMemorySize, GEMM_DSMEM);
        configured = 1;
    }

    precompute_kernel<<<32, 64>>>(qw, Wq, bq, Wf, bf);
    fused_kernel<<<B / 64, 128, GEMM_DSMEM>>>(xc, W1, b1, Wf, xq, out);
}